// round 8
// baseline (speedup 1.0000x reference)
#include <cuda_runtime.h>
#include <math.h>
#include <stdint.h>

#define BATCH   4
#define LSEQ    8192
#define DMODEL  1024
#define NHEADS  16
#define DHEAD   64
#define MROWS   (BATCH * LSEQ)          // 32768
#define NCHUNK  32
#define EPSV    1e-6f

// GEMM tiling: CTA 128(M) x 256(N), 8 warps (2x4), warp 64x64, k-stage 16.
#define BM      128
#define BN      256
#define KSTG    16
#define NSTG    (DMODEL / KSTG)         // 64
#define RSF     20                      // floats per smem row (80 B, conflict-free)
#define RSB     80
#define A_ROWS  BM
#define B_ROWS  BN
#define BOFF    (A_ROWS * RSB)          // 10240
#define STG_B   ((A_ROWS + B_ROWS) * RSB)   // 30720
#define GSMEM   (4 * STG_B)             // 122880

// ---------------- scratch (device globals; no allocations allowed) ----------
static __device__ float g_xr  [(size_t)MROWS * DMODEL];                 // tf32-rounded x
static __device__ float g_Wt  [(size_t)4 * DMODEL * DMODEL];            // [N,K] transposed+rounded W
static __device__ float g_Qf  [(size_t)MROWS * DMODEL];
static __device__ float g_Kf  [(size_t)MROWS * DMODEL];
static __device__ float g_V   [(size_t)MROWS * DMODEL];
static __device__ float g_attn[(size_t)MROWS * DMODEL];
static __device__ float g_KvP [(size_t)NCHUNK * BATCH * NHEADS * DHEAD * DHEAD];
static __device__ float g_K1P [(size_t)NCHUNK * BATCH * NHEADS * DHEAD];
static __device__ float g_Kv  [(size_t)BATCH * NHEADS * DHEAD * DHEAD];
static __device__ float g_K1  [(size_t)BATCH * NHEADS * DHEAD];

// ---------------- helpers ----------------------------------------------------
__device__ __forceinline__ float f2tf32(float x) {
    unsigned r;
    asm("cvt.rna.tf32.f32 %0, %1;" : "=r"(r) : "f"(x));
    return __uint_as_float(r);
}
__device__ __forceinline__ uint32_t smem_u32(const void* p) {
    uint32_t a;
    asm("{ .reg .u64 t; cvta.to.shared.u64 t, %1; cvt.u32.u64 %0, t; }" : "=r"(a) : "l"(p));
    return a;
}
__device__ __forceinline__ void cp_async16(uint32_t saddr, const void* gptr) {
    asm volatile("cp.async.cg.shared.global [%0], [%1], 16;" :: "r"(saddr), "l"(gptr));
}
__device__ __forceinline__ void cp_commit() { asm volatile("cp.async.commit_group;"); }
template <int N> __device__ __forceinline__ void cp_wait() {
    asm volatile("cp.async.wait_group %0;" :: "n"(N));
}
__device__ __forceinline__ void mma_tf32(float c[4],
                                         uint32_t a0, uint32_t a1, uint32_t a2, uint32_t a3,
                                         uint32_t b0, uint32_t b1)
{
    asm volatile("mma.sync.aligned.m16n8k8.row.col.f32.tf32.tf32.f32 "
                 "{%0,%1,%2,%3}, {%4,%5,%6,%7}, {%8,%9}, {%0,%1,%2,%3};"
                 : "+f"(c[0]), "+f"(c[1]), "+f"(c[2]), "+f"(c[3])
                 : "r"(a0), "r"(a1), "r"(a2), "r"(a3), "r"(b0), "r"(b1));
}
__device__ __forceinline__ void ldsm_x4(uint32_t& r0, uint32_t& r1, uint32_t& r2, uint32_t& r3,
                                        uint32_t addr)
{
    asm volatile("ldmatrix.sync.aligned.m8n8.x4.shared.b16 {%0,%1,%2,%3}, [%4];"
                 : "=r"(r0), "=r"(r1), "=r"(r2), "=r"(r3) : "r"(addr));
}
__device__ __forceinline__ void ldsm_x2(uint32_t& r0, uint32_t& r1, uint32_t addr)
{
    asm volatile("ldmatrix.sync.aligned.m8n8.x2.shared.b16 {%0,%1}, [%2];"
                 : "=r"(r0), "=r"(r1) : "r"(addr));
}

// ---------------- pre-passes --------------------------------------------------
__global__ void round_tf32_kernel(const float* __restrict__ in, float* __restrict__ out, int n4)
{
    int i = blockIdx.x * blockDim.x + threadIdx.x;
    if (i < n4) {
        float4 v = ((const float4*)in)[i];
        ((float4*)out)[i] = make_float4(f2tf32(v.x), f2tf32(v.y), f2tf32(v.z), f2tf32(v.w));
    }
}

// W [K,N] row-major -> Wt [N,K] (tf32-rounded)
__global__ void transpose_round_kernel(const float* __restrict__ src, float* __restrict__ dst)
{
    __shared__ float t[32][33];
    const int bx = blockIdx.x * 32, by = blockIdx.y * 32;
    const int tx = threadIdx.x, ty = threadIdx.y;
    #pragma unroll
    for (int j = ty; j < 32; j += 8)
        t[j][tx] = src[(size_t)(by + j) * DMODEL + bx + tx];
    __syncthreads();
    #pragma unroll
    for (int j = ty; j < 32; j += 8)
        dst[(size_t)(bx + j) * DMODEL + by + tx] = f2tf32(t[tx][j]);
}

// ---------------- TF32 mma.sync GEMM with ldmatrix ----------------------------
// C[M,N] = A[M,K] @ Bt^T, Bt stored [N,K] K-major, inputs tf32-rounded.
template <int PHI>
__global__ __launch_bounds__(256, 1)
void gemm_ldsm_kernel(const float* __restrict__ A, const float* __restrict__ Bt,
                      float* __restrict__ C)
{
    extern __shared__ __align__(16) float sm[];
    const uint32_t sb = smem_u32(sm);

    const int tid  = threadIdx.x;
    const int lane = tid & 31;
    const int wid  = tid >> 5;
    const int bm   = blockIdx.y * BM;
    const int bn   = blockIdx.x * BN;
    const int wm   = (wid >> 2) * 64;    // 0 or 64
    const int wn   = (wid & 3) * 64;     // 0,64,128,192

    // ---- staging indices: each thread 2 A-chunks + 4 B-chunks of 16B ----
    const int srow = tid >> 2;           // 0..63
    const int sch  = tid & 3;            // 16B chunk within 16-float k-row

    auto load_stage = [&](int s) {
        const uint32_t st = sb + (uint32_t)(s & 3) * STG_B;
        const int k0 = s * KSTG + sch * 4;
        cp_async16(st + (uint32_t)srow * RSB + sch * 16,
                   A + (size_t)(bm + srow) * DMODEL + k0);
        cp_async16(st + (uint32_t)(srow + 64) * RSB + sch * 16,
                   A + (size_t)(bm + srow + 64) * DMODEL + k0);
        #pragma unroll
        for (int j = 0; j < 4; j++) {
            const int r = srow + j * 64;
            cp_async16(st + BOFF + (uint32_t)r * RSB + sch * 16,
                       Bt + (size_t)(bn + r) * DMODEL + k0);
        }
    };

    // ---- per-lane ldmatrix base offsets (bytes within a stage) ----
    // A x4: quadrants [r0-7,k0-3],[r8-15,k0-3],[r0-7,k4-7],[r8-15,k4-7]
    const uint32_t a_off = (uint32_t)(wm + ((lane >> 3) & 1) * 8 + (lane & 7)) * RSB
                         + (uint32_t)(lane >> 4) * 16;
    // B x2: [n0-7,k0-3],[n0-7,k4-7]; lanes 0-15 supply addresses
    const uint32_t b_off = BOFF + (uint32_t)(wn + (lane & 7)) * RSB
                         + (uint32_t)((lane >> 3) & 1) * 16;

    float acc[4][8][4];
    #pragma unroll
    for (int mt = 0; mt < 4; mt++)
        #pragma unroll
        for (int nt = 0; nt < 8; nt++)
            #pragma unroll
            for (int i = 0; i < 4; i++) acc[mt][nt][i] = 0.f;

    // prologue: stages 0..2
    load_stage(0); cp_commit();
    load_stage(1); cp_commit();
    load_stage(2); cp_commit();

    #pragma unroll 1
    for (int c = 0; c < NSTG; c++) {
        cp_wait<2>();                    // stage c complete
        __syncthreads();                 // all warps done with stage c-1 too

        if (c + 3 < NSTG) load_stage(c + 3);   // reuses buffer (c-1)&3 — safe
        cp_commit();

        const uint32_t st = sb + (uint32_t)(c & 3) * STG_B;
        #pragma unroll
        for (int ks = 0; ks < 2; ks++) {
            const uint32_t ko = (uint32_t)ks * 32;   // 8 k-words
            uint32_t bfr[8][2];
            #pragma unroll
            for (int nt = 0; nt < 8; nt++)
                ldsm_x2(bfr[nt][0], bfr[nt][1], st + b_off + nt * (8 * RSB) + ko);
            #pragma unroll
            for (int mt = 0; mt < 4; mt++) {
                uint32_t a0, a1, a2, a3;
                ldsm_x4(a0, a1, a2, a3, st + a_off + mt * (16 * RSB) + ko);
                #pragma unroll
                for (int nt = 0; nt < 8; nt++)
                    mma_tf32(acc[mt][nt], a0, a1, a2, a3, bfr[nt][0], bfr[nt][1]);
            }
        }
    }

    // ---- epilogue ----
    const int lr = lane >> 2;
    const int lc = lane & 3;
    #pragma unroll
    for (int mt = 0; mt < 4; mt++) {
        #pragma unroll
        for (int nt = 0; nt < 8; nt++) {
            const int row0 = bm + wm + mt * 16 + lr;
            const int col  = bn + wn + nt * 8 + lc * 2;
            float v[4];
            #pragma unroll
            for (int i = 0; i < 4; i++) {
                float t = acc[mt][nt][i];
                if (PHI) t = (t > 0.f) ? (t + 1.f) : __expf(t);   // elu(x)+1
                v[i] = t;
            }
            *(float2*)(C + (size_t)row0 * DMODEL + col)       = make_float2(v[0], v[1]);
            *(float2*)(C + (size_t)(row0 + 8) * DMODEL + col) = make_float2(v[2], v[3]);
        }
    }
}

// ---------------- Kv / K1 split-K partial reduction -------------------------
__global__ __launch_bounds__(256, 4)
void kv_reduce_kernel()
{
    const int chunk = blockIdx.x;
    const int h     = blockIdx.y;
    const int b     = blockIdx.z;
    const int bh    = b * NHEADS + h;
    const int tid   = threadIdx.x;

    __shared__ float sK[64][65];
    __shared__ float sV[64][65];

    const int tm = (tid >> 4) * 4;
    const int tn = (tid & 15) * 4;

    float acc[4][4];
    #pragma unroll
    for (int i = 0; i < 4; i++)
        #pragma unroll
        for (int j = 0; j < 4; j++) acc[i][j] = 0.f;
    float k1acc = 0.f;

    const int SUBS = (LSEQ / NCHUNK) / 64;   // 4
    for (int sub = 0; sub < SUBS; sub++) {
        const int l0 = chunk * (LSEQ / NCHUNK) + sub * 64;
        for (int i = tid; i < 64 * 16; i += 256) {
            int r  = i >> 4;
            int c4 = (i & 15) << 2;
            size_t base = ((size_t)b * LSEQ + l0 + r) * DMODEL + h * DHEAD + c4;
            float4 kv = *(const float4*)(g_Kf + base);
            sK[r][c4+0]=kv.x; sK[r][c4+1]=kv.y; sK[r][c4+2]=kv.z; sK[r][c4+3]=kv.w;
            float4 vv = *(const float4*)(g_V + base);
            sV[r][c4+0]=vv.x; sV[r][c4+1]=vv.y; sV[r][c4+2]=vv.z; sV[r][c4+3]=vv.w;
        }
        __syncthreads();

        #pragma unroll 4
        for (int l = 0; l < 64; l++) {
            float a0 = sK[l][tm+0], a1 = sK[l][tm+1], a2 = sK[l][tm+2], a3 = sK[l][tm+3];
            float b0 = sV[l][tn+0], b1 = sV[l][tn+1], b2 = sV[l][tn+2], b3 = sV[l][tn+3];
            acc[0][0]+=a0*b0; acc[0][1]+=a0*b1; acc[0][2]+=a0*b2; acc[0][3]+=a0*b3;
            acc[1][0]+=a1*b0; acc[1][1]+=a1*b1; acc[1][2]+=a1*b2; acc[1][3]+=a1*b3;
            acc[2][0]+=a2*b0; acc[2][1]+=a2*b1; acc[2][2]+=a2*b2; acc[2][3]+=a2*b3;
            acc[3][0]+=a3*b0; acc[3][1]+=a3*b1; acc[3][2]+=a3*b2; acc[3][3]+=a3*b3;
        }
        if (tid < 64) {
            #pragma unroll 4
            for (int l = 0; l < 64; l++) k1acc += sK[l][tid];
        }
        __syncthreads();
    }

    #pragma unroll
    for (int i = 0; i < 4; i++)
        #pragma unroll
        for (int j = 0; j < 4; j++)
            g_KvP[(((size_t)chunk * (BATCH*NHEADS) + bh) * DHEAD + tm + i) * DHEAD + tn + j] = acc[i][j];
    if (tid < 64)
        g_K1P[((size_t)chunk * (BATCH*NHEADS) + bh) * DHEAD + tid] = k1acc;
}

__global__ void kv_finalize_kernel()
{
    const int i = blockIdx.x * blockDim.x + threadIdx.x;
    const int KV_ELEMS = BATCH * NHEADS * DHEAD * DHEAD;
    const int K1_ELEMS = BATCH * NHEADS * DHEAD;
    if (i < KV_ELEMS) {
        float s = 0.f;
        #pragma unroll
        for (int c = 0; c < NCHUNK; c++) s += g_KvP[(size_t)c * KV_ELEMS + i];
        g_Kv[i] = s;
    }
    if (i < K1_ELEMS) {
        float s = 0.f;
        #pragma unroll
        for (int c = 0; c < NCHUNK; c++) s += g_K1P[(size_t)c * K1_ELEMS + i];
        g_K1[i] = s;
    }
}

// ---------------- apply: attn = (Qf @ Kv) / (Qf @ K1 + eps), tf32-rounded ----
__global__ __launch_bounds__(256, 4)
void attn_apply_kernel()
{
    const int lt = blockIdx.x;
    const int h  = blockIdx.y;
    const int b  = blockIdx.z;
    const int bh = b * NHEADS + h;
    const int tid = threadIdx.x;

    __shared__ float sQ [64][65];
    __shared__ float sKv[64][65];
    __shared__ float sK1[64];
    __shared__ float sden[64];

    for (int i = tid; i < 64 * 16; i += 256) {
        int r  = i >> 4;
        int c4 = (i & 15) << 2;
        size_t qbase = ((size_t)b * LSEQ + lt * 64 + r) * DMODEL + h * DHEAD + c4;
        float4 qv = *(const float4*)(g_Qf + qbase);
        sQ[r][c4+0]=qv.x; sQ[r][c4+1]=qv.y; sQ[r][c4+2]=qv.z; sQ[r][c4+3]=qv.w;
        float4 kv = *(const float4*)(g_Kv + ((size_t)bh * DHEAD + r) * DHEAD + c4);
        sKv[r][c4+0]=kv.x; sKv[r][c4+1]=kv.y; sKv[r][c4+2]=kv.z; sKv[r][c4+3]=kv.w;
    }
    if (tid < 64) sK1[tid] = g_K1[(size_t)bh * DHEAD + tid];
    __syncthreads();

    if (tid < 64) {
        float d = 0.f;
        #pragma unroll
        for (int m = 0; m < 64; m++) d += sQ[tid][m] * sK1[m];
        sden[tid] = d + EPSV;
    }
    __syncthreads();

    const int tm = (tid >> 4) * 4;
    const int tn = (tid & 15) * 4;
    float acc[4][4];
    #pragma unroll
    for (int i = 0; i < 4; i++)
        #pragma unroll
        for (int j = 0; j < 4; j++) acc[i][j] = 0.f;

    #pragma unroll 4
    for (int m = 0; m < 64; m++) {
        float a0 = sQ[tm+0][m], a1 = sQ[tm+1][m], a2 = sQ[tm+2][m], a3 = sQ[tm+3][m];
        float b0 = sKv[m][tn+0], b1 = sKv[m][tn+1], b2 = sKv[m][tn+2], b3 = sKv[m][tn+3];
        acc[0][0]+=a0*b0; acc[0][1]+=a0*b1; acc[0][2]+=a0*b2; acc[0][3]+=a0*b3;
        acc[1][0]+=a1*b0; acc[1][1]+=a1*b1; acc[1][2]+=a1*b2; acc[1][3]+=a1*b3;
        acc[2][0]+=a2*b0; acc[2][1]+=a2*b1; acc[2][2]+=a2*b2; acc[2][3]+=a2*b3;
        acc[3][0]+=a3*b0; acc[3][1]+=a3*b1; acc[3][2]+=a3*b2; acc[3][3]+=a3*b3;
    }

    #pragma unroll
    for (int i = 0; i < 4; i++) {
        float inv = 1.f / sden[tm + i];
        size_t base = ((size_t)b * LSEQ + lt * 64 + tm + i) * DMODEL + h * DHEAD + tn;
        *(float4*)(g_attn + base) = make_float4(f2tf32(acc[i][0]*inv), f2tf32(acc[i][1]*inv),
                                                f2tf32(acc[i][2]*inv), f2tf32(acc[i][3]*inv));
    }
}

// ---------------- launch ------------------------------------------------------
extern "C" void kernel_launch(void* const* d_in, const int* in_sizes, int n_in,
                              void* d_out, int out_size)
{
    const float* x  = (const float*)d_in[0];
    const float* Wq = (const float*)d_in[1];
    const float* Wk = (const float*)d_in[2];
    const float* Wv = (const float*)d_in[3];
    const float* Wo = (const float*)d_in[4];
    float* out = (float*)d_out;

    float *pXr, *pWt, *pQf, *pKf, *pV, *pAttn;
    cudaGetSymbolAddress((void**)&pXr,   g_xr);
    cudaGetSymbolAddress((void**)&pWt,   g_Wt);
    cudaGetSymbolAddress((void**)&pQf,   g_Qf);
    cudaGetSymbolAddress((void**)&pKf,   g_Kf);
    cudaGetSymbolAddress((void**)&pV,    g_V);
    cudaGetSymbolAddress((void**)&pAttn, g_attn);

    cudaFuncSetAttribute(gemm_ldsm_kernel<0>, cudaFuncAttributeMaxDynamicSharedMemorySize, GSMEM);
    cudaFuncSetAttribute(gemm_ldsm_kernel<1>, cudaFuncAttributeMaxDynamicSharedMemorySize, GSMEM);

    const size_t WN = (size_t)DMODEL * DMODEL;

    // pre-round x; transpose+round weights to [N,K]
    round_tf32_kernel<<<(MROWS * DMODEL / 4 + 255) / 256, 256>>>(x, pXr, MROWS * DMODEL / 4);
    dim3 tgrid(DMODEL / 32, DMODEL / 32), tblk(32, 8);
    transpose_round_kernel<<<tgrid, tblk>>>(Wq, pWt + 0 * WN);
    transpose_round_kernel<<<tgrid, tblk>>>(Wk, pWt + 1 * WN);
    transpose_round_kernel<<<tgrid, tblk>>>(Wv, pWt + 2 * WN);
    transpose_round_kernel<<<tgrid, tblk>>>(Wo, pWt + 3 * WN);

    dim3 ggrid(DMODEL / BN, MROWS / BM);   // (4, 256)

    gemm_ldsm_kernel<1><<<ggrid, 256, GSMEM>>>(pXr, pWt + 0 * WN, pQf);
    gemm_ldsm_kernel<1><<<ggrid, 256, GSMEM>>>(pXr, pWt + 1 * WN, pKf);
    gemm_ldsm_kernel<0><<<ggrid, 256, GSMEM>>>(pXr, pWt + 2 * WN, pV);

    kv_reduce_kernel<<<dim3(NCHUNK, NHEADS, BATCH), 256>>>();
    kv_finalize_kernel<<<(BATCH*NHEADS*DHEAD*DHEAD + 255) / 256, 256>>>();

    attn_apply_kernel<<<dim3(LSEQ / 64, NHEADS, BATCH), 256>>>();

    gemm_ldsm_kernel<0><<<ggrid, 256, GSMEM>>>(pAttn, pWt + 3 * WN, out);
}

// round 10
// speedup vs baseline: 1.7620x; 1.7620x over previous
#include <cuda_runtime.h>
#include <cuda_fp16.h>
#include <math.h>
#include <stdint.h>

#define BATCH   4
#define LSEQ    8192
#define DMODEL  1024
#define NHEADS  16
#define DHEAD   64
#define MROWS   (BATCH * LSEQ)          // 32768
#define NCHUNK  32
#define EPSV    1e-6f

// GEMM tiling: CTA 128x128, 8 warps (2x4), warp 64x32, k-stage 32 (fp16).
#define BM      128
#define BN      128
#define KSTG    32
#define NSTG    (DMODEL / KSTG)         // 32
#define RSB     80                      // bytes per smem row (64 data + 16 pad)
#define BOFF    (BM * RSB)              // 10240
#define STG_B   ((BM + BN) * RSB)       // 20480
#define GSMEM   (4 * STG_B)             // 81920

// ---------------- scratch (device globals; no allocations allowed) ----------
static __device__ __half g_xh  [(size_t)MROWS * DMODEL];                // fp16 x
static __device__ __half g_Wth [(size_t)4 * DMODEL * DMODEL];           // [N,K] fp16 weights
static __device__ __half g_ath [(size_t)MROWS * DMODEL];                // fp16 attn out
static __device__ float  g_Qf  [(size_t)MROWS * DMODEL];
static __device__ float  g_Kf  [(size_t)MROWS * DMODEL];
static __device__ float  g_V   [(size_t)MROWS * DMODEL];
static __device__ float  g_KvP [(size_t)NCHUNK * BATCH * NHEADS * DHEAD * DHEAD];
static __device__ float  g_K1P [(size_t)NCHUNK * BATCH * NHEADS * DHEAD];
static __device__ float  g_Kv  [(size_t)BATCH * NHEADS * DHEAD * DHEAD];
static __device__ float  g_K1  [(size_t)BATCH * NHEADS * DHEAD];

// ---------------- helpers ----------------------------------------------------
__device__ __forceinline__ uint32_t smem_u32(const void* p) {
    uint32_t a;
    asm("{ .reg .u64 t; cvta.to.shared.u64 t, %1; cvt.u32.u64 %0, t; }" : "=r"(a) : "l"(p));
    return a;
}
__device__ __forceinline__ void cp_async16(uint32_t saddr, const void* gptr) {
    asm volatile("cp.async.cg.shared.global [%0], [%1], 16;" :: "r"(saddr), "l"(gptr));
}
__device__ __forceinline__ void cp_commit() { asm volatile("cp.async.commit_group;"); }
template <int N> __device__ __forceinline__ void cp_wait() {
    asm volatile("cp.async.wait_group %0;" :: "n"(N));
}
__device__ __forceinline__ void mma_f16(float c[4],
                                        uint32_t a0, uint32_t a1, uint32_t a2, uint32_t a3,
                                        uint32_t b0, uint32_t b1)
{
    asm volatile("mma.sync.aligned.m16n8k16.row.col.f32.f16.f16.f32 "
                 "{%0,%1,%2,%3}, {%4,%5,%6,%7}, {%8,%9}, {%0,%1,%2,%3};"
                 : "+f"(c[0]), "+f"(c[1]), "+f"(c[2]), "+f"(c[3])
                 : "r"(a0), "r"(a1), "r"(a2), "r"(a3), "r"(b0), "r"(b1));
}
__device__ __forceinline__ void ldsm_x4(uint32_t& r0, uint32_t& r1, uint32_t& r2, uint32_t& r3,
                                        uint32_t addr)
{
    asm volatile("ldmatrix.sync.aligned.m8n8.x4.shared.b16 {%0,%1,%2,%3}, [%4];"
                 : "=r"(r0), "=r"(r1), "=r"(r2), "=r"(r3) : "r"(addr));
}

// ---------------- pre-passes --------------------------------------------------
__global__ void to_half_kernel(const float* __restrict__ in, __half* __restrict__ out, int n4)
{
    int i = blockIdx.x * blockDim.x + threadIdx.x;
    if (i < n4) {
        float4 v = ((const float4*)in)[i];
        __half2 h0 = __floats2half2_rn(v.x, v.y);
        __half2 h1 = __floats2half2_rn(v.z, v.w);
        ((uint2*)out)[i] = make_uint2(*(uint32_t*)&h0, *(uint32_t*)&h1);
    }
}

// W [K,N] f32 row-major -> Wt [N,K] fp16
__global__ void transpose_half_kernel(const float* __restrict__ src, __half* __restrict__ dst)
{
    __shared__ float t[32][33];
    const int bx = blockIdx.x * 32, by = blockIdx.y * 32;
    const int tx = threadIdx.x, ty = threadIdx.y;
    #pragma unroll
    for (int j = ty; j < 32; j += 8)
        t[j][tx] = src[(size_t)(by + j) * DMODEL + bx + tx];
    __syncthreads();
    #pragma unroll
    for (int j = ty; j < 32; j += 8)
        dst[(size_t)(bx + j) * DMODEL + by + tx] = __float2half_rn(t[tx][j]);
}

// ---------------- fp16 mma.sync GEMM with ldmatrix ---------------------------
// C[M,N] = A[M,K] @ Bt^T, Bt stored [N,K] K-major (== B col-major), f32 acc.
template <int PHI>
__global__ __launch_bounds__(256, 2)
void gemm_f16_kernel(const __half* __restrict__ A, const __half* __restrict__ Bt,
                     float* __restrict__ C)
{
    extern __shared__ __align__(16) char smc[];
    const uint32_t sb = smem_u32(smc);

    const int tid  = threadIdx.x;
    const int lane = tid & 31;
    const int wid  = tid >> 5;
    const int bm   = blockIdx.y * BM;
    const int bn   = blockIdx.x * BN;
    const int wm   = (wid >> 2) * 64;    // 0 or 64
    const int wn   = (wid & 3) * 32;     // 0,32,64,96

    // staging: 1024 x 16B chunks per stage, 4 per thread
    const int srow = tid >> 2;           // 0..63
    const int sch  = tid & 3;            // 16B chunk (8 halves)

    auto load_stage = [&](int s) {
        const uint32_t st = sb + (uint32_t)(s & 3) * STG_B;
        const int k0 = s * KSTG + sch * 8;
        cp_async16(st + (uint32_t)srow * RSB + sch * 16,
                   A + (size_t)(bm + srow) * DMODEL + k0);
        cp_async16(st + (uint32_t)(srow + 64) * RSB + sch * 16,
                   A + (size_t)(bm + srow + 64) * DMODEL + k0);
        cp_async16(st + BOFF + (uint32_t)srow * RSB + sch * 16,
                   Bt + (size_t)(bn + srow) * DMODEL + k0);
        cp_async16(st + BOFF + (uint32_t)(srow + 64) * RSB + sch * 16,
                   Bt + (size_t)(bn + srow + 64) * DMODEL + k0);
    };

    // per-lane ldmatrix offsets within a stage (bytes)
    // A x4 quadrants: (m0-7,k0-7),(m8-15,k0-7),(m0-7,k8-15),(m8-15,k8-15) -> a0..a3
    const uint32_t a_off = (uint32_t)(wm + ((lane >> 3) & 1) * 8 + (lane & 7)) * RSB
                         + (uint32_t)(lane >> 4) * 16;
    // B x4 (non-trans): octets -> (n0-7,k0-7),(n0-7,k8-15),(n8-15,k0-7),(n8-15,k8-15)
    //   = nt0.b0, nt0.b1, nt1.b0, nt1.b1   (smem row = n, already col-major B)
    const uint32_t b_off = BOFF + (uint32_t)(wn + (lane >> 4) * 8 + (lane & 7)) * RSB
                         + (uint32_t)((lane >> 3) & 1) * 16;

    float acc[4][4][4];
    #pragma unroll
    for (int mt = 0; mt < 4; mt++)
        #pragma unroll
        for (int nt = 0; nt < 4; nt++)
            #pragma unroll
            for (int i = 0; i < 4; i++) acc[mt][nt][i] = 0.f;

    load_stage(0); cp_commit();
    load_stage(1); cp_commit();
    load_stage(2); cp_commit();

    #pragma unroll 1
    for (int c = 0; c < NSTG; c++) {
        cp_wait<2>();
        __syncthreads();

        if (c + 3 < NSTG) load_stage(c + 3);
        cp_commit();

        const uint32_t st = sb + (uint32_t)(c & 3) * STG_B;
        #pragma unroll
        for (int ks = 0; ks < 2; ks++) {
            const uint32_t ko = (uint32_t)ks * 32;   // 16 halves = 32 B
            uint32_t bfr[4][2];
            // two x4 (non-trans) cover nt 0..3 (each: 2 n-tiles x full k16)
            ldsm_x4(bfr[0][0], bfr[0][1], bfr[1][0], bfr[1][1], st + b_off + ko);
            ldsm_x4(bfr[2][0], bfr[2][1], bfr[3][0], bfr[3][1], st + b_off + 16 * RSB + ko);
            #pragma unroll
            for (int mt = 0; mt < 4; mt++) {
                uint32_t a0, a1, a2, a3;
                ldsm_x4(a0, a1, a2, a3, st + a_off + mt * (16 * RSB) + ko);
                #pragma unroll
                for (int nt = 0; nt < 4; nt++)
                    mma_f16(acc[mt][nt], a0, a1, a2, a3, bfr[nt][0], bfr[nt][1]);
            }
        }
    }

    // epilogue
    const int lr = lane >> 2;
    const int lc = lane & 3;
    #pragma unroll
    for (int mt = 0; mt < 4; mt++) {
        #pragma unroll
        for (int nt = 0; nt < 4; nt++) {
            const int row0 = bm + wm + mt * 16 + lr;
            const int col  = bn + wn + nt * 8 + lc * 2;
            float v[4];
            #pragma unroll
            for (int i = 0; i < 4; i++) {
                float t = acc[mt][nt][i];
                if (PHI) t = (t > 0.f) ? (t + 1.f) : __expf(t);   // elu(x)+1
                v[i] = t;
            }
            *(float2*)(C + (size_t)row0 * DMODEL + col)       = make_float2(v[0], v[1]);
            *(float2*)(C + (size_t)(row0 + 8) * DMODEL + col) = make_float2(v[2], v[3]);
        }
    }
}

// ---------------- Kv / K1 split-K partial reduction -------------------------
__global__ __launch_bounds__(256, 4)
void kv_reduce_kernel()
{
    const int chunk = blockIdx.x;
    const int h     = blockIdx.y;
    const int b     = blockIdx.z;
    const int bh    = b * NHEADS + h;
    const int tid   = threadIdx.x;

    __shared__ float sK[64][65];
    __shared__ float sV[64][65];

    const int tm = (tid >> 4) * 4;
    const int tn = (tid & 15) * 4;

    float acc[4][4];
    #pragma unroll
    for (int i = 0; i < 4; i++)
        #pragma unroll
        for (int j = 0; j < 4; j++) acc[i][j] = 0.f;
    float k1acc = 0.f;

    const int SUBS = (LSEQ / NCHUNK) / 64;   // 4
    for (int sub = 0; sub < SUBS; sub++) {
        const int l0 = chunk * (LSEQ / NCHUNK) + sub * 64;
        for (int i = tid; i < 64 * 16; i += 256) {
            int r  = i >> 4;
            int c4 = (i & 15) << 2;
            size_t base = ((size_t)b * LSEQ + l0 + r) * DMODEL + h * DHEAD + c4;
            float4 kv = *(const float4*)(g_Kf + base);
            sK[r][c4+0]=kv.x; sK[r][c4+1]=kv.y; sK[r][c4+2]=kv.z; sK[r][c4+3]=kv.w;
            float4 vv = *(const float4*)(g_V + base);
            sV[r][c4+0]=vv.x; sV[r][c4+1]=vv.y; sV[r][c4+2]=vv.z; sV[r][c4+3]=vv.w;
        }
        __syncthreads();

        #pragma unroll 4
        for (int l = 0; l < 64; l++) {
            float a0 = sK[l][tm+0], a1 = sK[l][tm+1], a2 = sK[l][tm+2], a3 = sK[l][tm+3];
            float b0 = sV[l][tn+0], b1 = sV[l][tn+1], b2 = sV[l][tn+2], b3 = sV[l][tn+3];
            acc[0][0]+=a0*b0; acc[0][1]+=a0*b1; acc[0][2]+=a0*b2; acc[0][3]+=a0*b3;
            acc[1][0]+=a1*b0; acc[1][1]+=a1*b1; acc[1][2]+=a1*b2; acc[1][3]+=a1*b3;
            acc[2][0]+=a2*b0; acc[2][1]+=a2*b1; acc[2][2]+=a2*b2; acc[2][3]+=a2*b3;
            acc[3][0]+=a3*b0; acc[3][1]+=a3*b1; acc[3][2]+=a3*b2; acc[3][3]+=a3*b3;
        }
        if (tid < 64) {
            #pragma unroll 4
            for (int l = 0; l < 64; l++) k1acc += sK[l][tid];
        }
        __syncthreads();
    }

    #pragma unroll
    for (int i = 0; i < 4; i++)
        #pragma unroll
        for (int j = 0; j < 4; j++)
            g_KvP[(((size_t)chunk * (BATCH*NHEADS) + bh) * DHEAD + tm + i) * DHEAD + tn + j] = acc[i][j];
    if (tid < 64)
        g_K1P[((size_t)chunk * (BATCH*NHEADS) + bh) * DHEAD + tid] = k1acc;
}

__global__ void kv_finalize_kernel()
{
    const int i = blockIdx.x * blockDim.x + threadIdx.x;
    const int KV_ELEMS = BATCH * NHEADS * DHEAD * DHEAD;
    const int K1_ELEMS = BATCH * NHEADS * DHEAD;
    if (i < KV_ELEMS) {
        float s = 0.f;
        #pragma unroll
        for (int c = 0; c < NCHUNK; c++) s += g_KvP[(size_t)c * KV_ELEMS + i];
        g_Kv[i] = s;
    }
    if (i < K1_ELEMS) {
        float s = 0.f;
        #pragma unroll
        for (int c = 0; c < NCHUNK; c++) s += g_K1P[(size_t)c * K1_ELEMS + i];
        g_K1[i] = s;
    }
}

// ---------------- apply: attn = (Qf @ Kv) / (Qf @ K1 + eps) -> fp16 ----------
__global__ __launch_bounds__(256, 4)
void attn_apply_kernel()
{
    const int lt = blockIdx.x;
    const int h  = blockIdx.y;
    const int b  = blockIdx.z;
    const int bh = b * NHEADS + h;
    const int tid = threadIdx.x;

    __shared__ float sQ [64][65];
    __shared__ float sKv[64][65];
    __shared__ float sK1[64];
    __shared__ float sden[64];

    for (int i = tid; i < 64 * 16; i += 256) {
        int r  = i >> 4;
        int c4 = (i & 15) << 2;
        size_t qbase = ((size_t)b * LSEQ + lt * 64 + r) * DMODEL + h * DHEAD + c4;
        float4 qv = *(const float4*)(g_Qf + qbase);
        sQ[r][c4+0]=qv.x; sQ[r][c4+1]=qv.y; sQ[r][c4+2]=qv.z; sQ[r][c4+3]=qv.w;
        float4 kv = *(const float4*)(g_Kv + ((size_t)bh * DHEAD + r) * DHEAD + c4);
        sKv[r][c4+0]=kv.x; sKv[r][c4+1]=kv.y; sKv[r][c4+2]=kv.z; sKv[r][c4+3]=kv.w;
    }
    if (tid < 64) sK1[tid] = g_K1[(size_t)bh * DHEAD + tid];
    __syncthreads();

    if (tid < 64) {
        float d = 0.f;
        #pragma unroll
        for (int m = 0; m < 64; m++) d += sQ[tid][m] * sK1[m];
        sden[tid] = d + EPSV;
    }
    __syncthreads();

    const int tm = (tid >> 4) * 4;
    const int tn = (tid & 15) * 4;
    float acc[4][4];
    #pragma unroll
    for (int i = 0; i < 4; i++)
        #pragma unroll
        for (int j = 0; j < 4; j++) acc[i][j] = 0.f;

    #pragma unroll 4
    for (int m = 0; m < 64; m++) {
        float a0 = sQ[tm+0][m], a1 = sQ[tm+1][m], a2 = sQ[tm+2][m], a3 = sQ[tm+3][m];
        float b0 = sKv[m][tn+0], b1 = sKv[m][tn+1], b2 = sKv[m][tn+2], b3 = sKv[m][tn+3];
        acc[0][0]+=a0*b0; acc[0][1]+=a0*b1; acc[0][2]+=a0*b2; acc[0][3]+=a0*b3;
        acc[1][0]+=a1*b0; acc[1][1]+=a1*b1; acc[1][2]+=a1*b2; acc[1][3]+=a1*b3;
        acc[2][0]+=a2*b0; acc[2][1]+=a2*b1; acc[2][2]+=a2*b2; acc[2][3]+=a2*b3;
        acc[3][0]+=a3*b0; acc[3][1]+=a3*b1; acc[3][2]+=a3*b2; acc[3][3]+=a3*b3;
    }

    #pragma unroll
    for (int i = 0; i < 4; i++) {
        float inv = 1.f / sden[tm + i];
        size_t base = ((size_t)b * LSEQ + lt * 64 + tm + i) * DMODEL + h * DHEAD + tn;
        __half2 h0 = __floats2half2_rn(acc[i][0]*inv, acc[i][1]*inv);
        __half2 h1 = __floats2half2_rn(acc[i][2]*inv, acc[i][3]*inv);
        *(uint2*)(g_ath + base) = make_uint2(*(uint32_t*)&h0, *(uint32_t*)&h1);
    }
}

// ---------------- launch ------------------------------------------------------
extern "C" void kernel_launch(void* const* d_in, const int* in_sizes, int n_in,
                              void* d_out, int out_size)
{
    const float* x  = (const float*)d_in[0];
    const float* Wq = (const float*)d_in[1];
    const float* Wk = (const float*)d_in[2];
    const float* Wv = (const float*)d_in[3];
    const float* Wo = (const float*)d_in[4];
    float* out = (float*)d_out;

    __half *pXh, *pWth, *pAth;
    float  *pQf, *pKf, *pV;
    cudaGetSymbolAddress((void**)&pXh,  g_xh);
    cudaGetSymbolAddress((void**)&pWth, g_Wth);
    cudaGetSymbolAddress((void**)&pAth, g_ath);
    cudaGetSymbolAddress((void**)&pQf,  g_Qf);
    cudaGetSymbolAddress((void**)&pKf,  g_Kf);
    cudaGetSymbolAddress((void**)&pV,   g_V);

    cudaFuncSetAttribute(gemm_f16_kernel<0>, cudaFuncAttributeMaxDynamicSharedMemorySize, GSMEM);
    cudaFuncSetAttribute(gemm_f16_kernel<1>, cudaFuncAttributeMaxDynamicSharedMemorySize, GSMEM);

    const size_t WN = (size_t)DMODEL * DMODEL;

    // pre-convert operands to fp16 ([N,K] for weights)
    to_half_kernel<<<(MROWS * DMODEL / 4 + 255) / 256, 256>>>(x, pXh, MROWS * DMODEL / 4);
    dim3 tgrid(DMODEL / 32, DMODEL / 32), tblk(32, 8);
    transpose_half_kernel<<<tgrid, tblk>>>(Wq, pWth + 0 * WN);
    transpose_half_kernel<<<tgrid, tblk>>>(Wk, pWth + 1 * WN);
    transpose_half_kernel<<<tgrid, tblk>>>(Wv, pWth + 2 * WN);
    transpose_half_kernel<<<tgrid, tblk>>>(Wo, pWth + 3 * WN);

    dim3 ggrid(DMODEL / BN, MROWS / BM);   // (8, 256)

    gemm_f16_kernel<1><<<ggrid, 256, GSMEM>>>(pXh, pWth + 0 * WN, pQf);
    gemm_f16_kernel<1><<<ggrid, 256, GSMEM>>>(pXh, pWth + 1 * WN, pKf);
    gemm_f16_kernel<0><<<ggrid, 256, GSMEM>>>(pXh, pWth + 2 * WN, pV);

    kv_reduce_kernel<<<dim3(NCHUNK, NHEADS, BATCH), 256>>>();
    kv_finalize_kernel<<<(BATCH*NHEADS*DHEAD*DHEAD + 255) / 256, 256>>>();

    attn_apply_kernel<<<dim3(LSEQ / 64, NHEADS, BATCH), 256>>>();

    gemm_f16_kernel<0><<<ggrid, 256, GSMEM>>>(pAth, pWth + 3 * WN, out);
}

// round 13
// speedup vs baseline: 1.8256x; 1.0361x over previous
#include <cuda_runtime.h>
#include <cuda_fp16.h>
#include <math.h>
#include <stdint.h>

#define BATCH   4
#define LSEQ    8192
#define DMODEL  1024
#define NHEADS  16
#define DHEAD   64
#define MROWS   (BATCH * LSEQ)          // 32768
#define NCHUNK  32
#define EPSV    1e-6f

// GEMM tiling: CTA 128x128, 8 warps (2x4), warp 64x32, k-stage 32 (fp16).
#define BM      128
#define BN      128
#define KSTG    32
#define NSTG    (DMODEL / KSTG)         // 32
#define RSB     80                      // bytes per smem row (64 data + 16 pad)
#define BOFF    (BM * RSB)              // 10240
#define STG_B   ((BM + BN) * RSB)       // 20480
#define GSMEM   (4 * STG_B)             // 81920

// ---------------- scratch (device globals; no allocations allowed) ----------
static __device__ __half g_xh  [(size_t)MROWS * DMODEL];                // fp16 x
static __device__ __half g_Wth [(size_t)4 * DMODEL * DMODEL];           // [N,K] fp16 W (q,k,v,o)
static __device__ __half g_Qfh [(size_t)MROWS * DMODEL];                // fp16 phi(xWq)
static __device__ __half g_Kfh [(size_t)MROWS * DMODEL];                // fp16 phi(xWk)
static __device__ __half g_Vh  [(size_t)MROWS * DMODEL];                // fp16 xWv
static __device__ __half g_ath [(size_t)MROWS * DMODEL];                // fp16 attn out
static __device__ float  g_KvP [(size_t)NCHUNK * BATCH * NHEADS * DHEAD * DHEAD];
static __device__ float  g_K1P [(size_t)NCHUNK * BATCH * NHEADS * DHEAD];
static __device__ float  g_Kv  [(size_t)BATCH * NHEADS * DHEAD * DHEAD];
static __device__ float  g_K1  [(size_t)BATCH * NHEADS * DHEAD];

// ---------------- helpers ----------------------------------------------------
__device__ __forceinline__ uint32_t smem_u32(const void* p) {
    uint32_t a;
    asm("{ .reg .u64 t; cvta.to.shared.u64 t, %1; cvt.u32.u64 %0, t; }" : "=r"(a) : "l"(p));
    return a;
}
__device__ __forceinline__ void cp_async16(uint32_t saddr, const void* gptr) {
    asm volatile("cp.async.cg.shared.global [%0], [%1], 16;" :: "r"(saddr), "l"(gptr));
}
__device__ __forceinline__ void cp_commit() { asm volatile("cp.async.commit_group;"); }
template <int N> __device__ __forceinline__ void cp_wait() {
    asm volatile("cp.async.wait_group %0;" :: "n"(N));
}
__device__ __forceinline__ void mma_f16(float c[4],
                                        uint32_t a0, uint32_t a1, uint32_t a2, uint32_t a3,
                                        uint32_t b0, uint32_t b1)
{
    asm volatile("mma.sync.aligned.m16n8k16.row.col.f32.f16.f16.f32 "
                 "{%0,%1,%2,%3}, {%4,%5,%6,%7}, {%8,%9}, {%0,%1,%2,%3};"
                 : "+f"(c[0]), "+f"(c[1]), "+f"(c[2]), "+f"(c[3])
                 : "r"(a0), "r"(a1), "r"(a2), "r"(a3), "r"(b0), "r"(b1));
}
__device__ __forceinline__ void ldsm_x4(uint32_t& r0, uint32_t& r1, uint32_t& r2, uint32_t& r3,
                                        uint32_t addr)
{
    asm volatile("ldmatrix.sync.aligned.m8n8.x4.shared.b16 {%0,%1,%2,%3}, [%4];"
                 : "=r"(r0), "=r"(r1), "=r"(r2), "=r"(r3) : "r"(addr));
}
// 16 bytes = 8 halves -> 8 floats (correct uint4 unpack)
__device__ __forceinline__ void unpack8(float* dst, uint4 raw)
{
    float2 f;
    f = __half22float2(*(__half2*)&raw.x); dst[0]=f.x; dst[1]=f.y;
    f = __half22float2(*(__half2*)&raw.y); dst[2]=f.x; dst[3]=f.y;
    f = __half22float2(*(__half2*)&raw.z); dst[4]=f.x; dst[5]=f.y;
    f = __half22float2(*(__half2*)&raw.w); dst[6]=f.x; dst[7]=f.y;
}

// ---------------- pre-passes --------------------------------------------------
__global__ void to_half_kernel(const float* __restrict__ in, __half* __restrict__ out, int n4)
{
    int i = blockIdx.x * blockDim.x + threadIdx.x;
    if (i < n4) {
        float4 v = ((const float4*)in)[i];
        __half2 h0 = __floats2half2_rn(v.x, v.y);
        __half2 h1 = __floats2half2_rn(v.z, v.w);
        ((uint2*)out)[i] = make_uint2(*(uint32_t*)&h0, *(uint32_t*)&h1);
    }
}

// All 4 weights [K,N] f32 -> [N,K] fp16, z = which weight
__global__ void transpose_all_kernel(const float* __restrict__ Wq, const float* __restrict__ Wk,
                                     const float* __restrict__ Wv, const float* __restrict__ Wo,
                                     __half* __restrict__ dst)
{
    __shared__ float t[32][33];
    const float* src = (blockIdx.z == 0) ? Wq : (blockIdx.z == 1) ? Wk
                     : (blockIdx.z == 2) ? Wv : Wo;
    __half* d = dst + (size_t)blockIdx.z * DMODEL * DMODEL;
    const int bx = blockIdx.x * 32, by = blockIdx.y * 32;
    const int tx = threadIdx.x, ty = threadIdx.y;
    #pragma unroll
    for (int j = ty; j < 32; j += 8)
        t[j][tx] = src[(size_t)(by + j) * DMODEL + bx + tx];
    __syncthreads();
    #pragma unroll
    for (int j = ty; j < 32; j += 8)
        d[(size_t)(bx + j) * DMODEL + by + tx] = __float2half_rn(t[tx][j]);
}

// ---------------- fp16 mma.sync GEMM with ldmatrix ---------------------------
// MODE 0: C f32 (final Wo GEMM), no phi.
// MODE 1: fused QKV — output buffer + phi chosen by bn segment, fp16 out.
template <int MODE>
__global__ __launch_bounds__(256, 2)
void gemm_f16_kernel(const __half* __restrict__ A, const __half* __restrict__ Bt,
                     float* __restrict__ Cf)
{
    extern __shared__ __align__(16) char smc[];
    const uint32_t sb = smem_u32(smc);

    const int tid  = threadIdx.x;
    const int lane = tid & 31;
    const int wid  = tid >> 5;
    const int bm   = blockIdx.y * BM;
    const int bn   = blockIdx.x * BN;
    const int wm   = (wid >> 2) * 64;    // 0 or 64
    const int wn   = (wid & 3) * 32;     // 0,32,64,96

    const int srow = tid >> 2;           // 0..63
    const int sch  = tid & 3;            // 16B chunk (8 halves)

    auto load_stage = [&](int s) {
        const uint32_t st = sb + (uint32_t)(s & 3) * STG_B;
        const int k0 = s * KSTG + sch * 8;
        cp_async16(st + (uint32_t)srow * RSB + sch * 16,
                   A + (size_t)(bm + srow) * DMODEL + k0);
        cp_async16(st + (uint32_t)(srow + 64) * RSB + sch * 16,
                   A + (size_t)(bm + srow + 64) * DMODEL + k0);
        cp_async16(st + BOFF + (uint32_t)srow * RSB + sch * 16,
                   Bt + (size_t)(bn + srow) * DMODEL + k0);
        cp_async16(st + BOFF + (uint32_t)(srow + 64) * RSB + sch * 16,
                   Bt + (size_t)(bn + srow + 64) * DMODEL + k0);
    };

    // A x4 quadrants: (m0-7,k0-7),(m8-15,k0-7),(m0-7,k8-15),(m8-15,k8-15)
    const uint32_t a_off = (uint32_t)(wm + ((lane >> 3) & 1) * 8 + (lane & 7)) * RSB
                         + (uint32_t)(lane >> 4) * 16;
    // B x4 non-trans: (n0-7,k0-7),(n0-7,k8-15),(n8-15,k0-7),(n8-15,k8-15)
    const uint32_t b_off = BOFF + (uint32_t)(wn + (lane >> 4) * 8 + (lane & 7)) * RSB
                         + (uint32_t)((lane >> 3) & 1) * 16;

    float acc[4][4][4];
    #pragma unroll
    for (int mt = 0; mt < 4; mt++)
        #pragma unroll
        for (int nt = 0; nt < 4; nt++)
            #pragma unroll
            for (int i = 0; i < 4; i++) acc[mt][nt][i] = 0.f;

    load_stage(0); cp_commit();
    load_stage(1); cp_commit();
    load_stage(2); cp_commit();

    #pragma unroll 1
    for (int c = 0; c < NSTG; c++) {
        cp_wait<2>();
        __syncthreads();

        if (c + 3 < NSTG) load_stage(c + 3);
        cp_commit();

        const uint32_t st = sb + (uint32_t)(c & 3) * STG_B;
        #pragma unroll
        for (int ks = 0; ks < 2; ks++) {
            const uint32_t ko = (uint32_t)ks * 32;
            uint32_t bfr[4][2];
            ldsm_x4(bfr[0][0], bfr[0][1], bfr[1][0], bfr[1][1], st + b_off + ko);
            ldsm_x4(bfr[2][0], bfr[2][1], bfr[3][0], bfr[3][1], st + b_off + 16 * RSB + ko);
            #pragma unroll
            for (int mt = 0; mt < 4; mt++) {
                uint32_t a0, a1, a2, a3;
                ldsm_x4(a0, a1, a2, a3, st + a_off + mt * (16 * RSB) + ko);
                #pragma unroll
                for (int nt = 0; nt < 4; nt++)
                    mma_f16(acc[mt][nt], a0, a1, a2, a3, bfr[nt][0], bfr[nt][1]);
            }
        }
    }

    // ---- epilogue ----
    const int lr = lane >> 2;
    const int lc = lane & 3;

    if (MODE == 0) {
        #pragma unroll
        for (int mt = 0; mt < 4; mt++)
            #pragma unroll
            for (int nt = 0; nt < 4; nt++) {
                const int row0 = bm + wm + mt * 16 + lr;
                const int col  = bn + wn + nt * 8 + lc * 2;
                *(float2*)(Cf + (size_t)row0 * DMODEL + col) =
                    make_float2(acc[mt][nt][0], acc[mt][nt][1]);
                *(float2*)(Cf + (size_t)(row0 + 8) * DMODEL + col) =
                    make_float2(acc[mt][nt][2], acc[mt][nt][3]);
            }
    } else {
        const int seg = bn >> 10;             // 0=Q, 1=K, 2=V
        const int bnl = bn & 1023;
        __half* outp = (seg == 0) ? g_Qfh : (seg == 1) ? g_Kfh : g_Vh;
        const bool phi = (seg < 2);
        #pragma unroll
        for (int mt = 0; mt < 4; mt++)
            #pragma unroll
            for (int nt = 0; nt < 4; nt++) {
                const int row0 = bm + wm + mt * 16 + lr;
                const int col  = bnl + wn + nt * 8 + lc * 2;
                float v[4];
                #pragma unroll
                for (int i = 0; i < 4; i++) {
                    float t = acc[mt][nt][i];
                    if (phi) t = (t > 0.f) ? (t + 1.f) : __expf(t);   // elu+1
                    v[i] = t;
                }
                __half2 h0 = __floats2half2_rn(v[0], v[1]);
                __half2 h1 = __floats2half2_rn(v[2], v[3]);
                *(uint32_t*)(outp + (size_t)row0 * DMODEL + col)       = *(uint32_t*)&h0;
                *(uint32_t*)(outp + (size_t)(row0 + 8) * DMODEL + col) = *(uint32_t*)&h1;
            }
    }
}

// ---------------- Kv / K1 split-K partial reduction (fp16 in, f32 math) ------
__global__ __launch_bounds__(256, 4)
void kv_reduce_kernel()
{
    const int chunk = blockIdx.x;
    const int h     = blockIdx.y;
    const int b     = blockIdx.z;
    const int bh    = b * NHEADS + h;
    const int tid   = threadIdx.x;

    __shared__ float sK[64][65];
    __shared__ float sV[64][65];

    const int tm = (tid >> 4) * 4;
    const int tn = (tid & 15) * 4;

    float acc[4][4];
    #pragma unroll
    for (int i = 0; i < 4; i++)
        #pragma unroll
        for (int j = 0; j < 4; j++) acc[i][j] = 0.f;
    float k1acc = 0.f;

    const int SUBS = (LSEQ / NCHUNK) / 64;   // 4
    for (int sub = 0; sub < SUBS; sub++) {
        const int l0 = chunk * (LSEQ / NCHUNK) + sub * 64;
        for (int i = tid; i < 64 * 8; i += 256) {   // 8 halves = one uint4 (16 B)
            int r  = i >> 3;
            int c8 = (i & 7) << 3;
            size_t base = ((size_t)b * LSEQ + l0 + r) * DMODEL + h * DHEAD + c8;
            unpack8(&sK[r][c8], *(const uint4*)(g_Kfh + base));
            unpack8(&sV[r][c8], *(const uint4*)(g_Vh  + base));
        }
        __syncthreads();

        #pragma unroll 4
        for (int l = 0; l < 64; l++) {
            float a0 = sK[l][tm+0], a1 = sK[l][tm+1], a2 = sK[l][tm+2], a3 = sK[l][tm+3];
            float b0 = sV[l][tn+0], b1 = sV[l][tn+1], b2 = sV[l][tn+2], b3 = sV[l][tn+3];
            acc[0][0]+=a0*b0; acc[0][1]+=a0*b1; acc[0][2]+=a0*b2; acc[0][3]+=a0*b3;
            acc[1][0]+=a1*b0; acc[1][1]+=a1*b1; acc[1][2]+=a1*b2; acc[1][3]+=a1*b3;
            acc[2][0]+=a2*b0; acc[2][1]+=a2*b1; acc[2][2]+=a2*b2; acc[2][3]+=a2*b3;
            acc[3][0]+=a3*b0; acc[3][1]+=a3*b1; acc[3][2]+=a3*b2; acc[3][3]+=a3*b3;
        }
        if (tid < 64) {
            #pragma unroll 4
            for (int l = 0; l < 64; l++) k1acc += sK[l][tid];
        }
        __syncthreads();
    }

    #pragma unroll
    for (int i = 0; i < 4; i++)
        #pragma unroll
        for (int j = 0; j < 4; j++)
            g_KvP[(((size_t)chunk * (BATCH*NHEADS) + bh) * DHEAD + tm + i) * DHEAD + tn + j] = acc[i][j];
    if (tid < 64)
        g_K1P[((size_t)chunk * (BATCH*NHEADS) + bh) * DHEAD + tid] = k1acc;
}

__global__ void kv_finalize_kernel()
{
    const int i = blockIdx.x * blockDim.x + threadIdx.x;
    const int KV_ELEMS = BATCH * NHEADS * DHEAD * DHEAD;
    const int K1_ELEMS = BATCH * NHEADS * DHEAD;
    if (i < KV_ELEMS) {
        float s = 0.f;
        #pragma unroll
        for (int c = 0; c < NCHUNK; c++) s += g_KvP[(size_t)c * KV_ELEMS + i];
        g_Kv[i] = s;
    }
    if (i < K1_ELEMS) {
        float s = 0.f;
        #pragma unroll
        for (int c = 0; c < NCHUNK; c++) s += g_K1P[(size_t)c * K1_ELEMS + i];
        g_K1[i] = s;
    }
}

// ---------------- apply: attn = (Qf @ Kv) / (Qf @ K1 + eps) -> fp16 ----------
__global__ __launch_bounds__(256, 4)
void attn_apply_kernel()
{
    const int lt = blockIdx.x;
    const int h  = blockIdx.y;
    const int b  = blockIdx.z;
    const int bh = b * NHEADS + h;
    const int tid = threadIdx.x;

    __shared__ float sQ [64][65];
    __shared__ float sKv[64][65];
    __shared__ float sK1[64];
    __shared__ float sden[64];

    for (int i = tid; i < 64 * 8; i += 256) {        // Q: uint4 = 8 halves
        int r  = i >> 3;
        int c8 = (i & 7) << 3;
        size_t qbase = ((size_t)b * LSEQ + lt * 64 + r) * DMODEL + h * DHEAD + c8;
        unpack8(&sQ[r][c8], *(const uint4*)(g_Qfh + qbase));
    }
    for (int i = tid; i < 64 * 16; i += 256) {       // Kv f32
        int r  = i >> 4;
        int c4 = (i & 15) << 2;
        float4 kv = *(const float4*)(g_Kv + ((size_t)bh * DHEAD + r) * DHEAD + c4);
        sKv[r][c4+0]=kv.x; sKv[r][c4+1]=kv.y; sKv[r][c4+2]=kv.z; sKv[r][c4+3]=kv.w;
    }
    if (tid < 64) sK1[tid] = g_K1[(size_t)bh * DHEAD + tid];
    __syncthreads();

    if (tid < 64) {
        float d = 0.f;
        #pragma unroll
        for (int m = 0; m < 64; m++) d += sQ[tid][m] * sK1[m];
        sden[tid] = d + EPSV;
    }
    __syncthreads();

    const int tm = (tid >> 4) * 4;
    const int tn = (tid & 15) * 4;
    float acc[4][4];
    #pragma unroll
    for (int i = 0; i < 4; i++)
        #pragma unroll
        for (int j = 0; j < 4; j++) acc[i][j] = 0.f;

    #pragma unroll 4
    for (int m = 0; m < 64; m++) {
        float a0 = sQ[tm+0][m], a1 = sQ[tm+1][m], a2 = sQ[tm+2][m], a3 = sQ[tm+3][m];
        float b0 = sKv[m][tn+0], b1 = sKv[m][tn+1], b2 = sKv[m][tn+2], b3 = sKv[m][tn+3];
        acc[0][0]+=a0*b0; acc[0][1]+=a0*b1; acc[0][2]+=a0*b2; acc[0][3]+=a0*b3;
        acc[1][0]+=a1*b0; acc[1][1]+=a1*b1; acc[1][2]+=a1*b2; acc[1][3]+=a1*b3;
        acc[2][0]+=a2*b0; acc[2][1]+=a2*b1; acc[2][2]+=a2*b2; acc[2][3]+=a2*b3;
        acc[3][0]+=a3*b0; acc[3][1]+=a3*b1; acc[3][2]+=a3*b2; acc[3][3]+=a3*b3;
    }

    #pragma unroll
    for (int i = 0; i < 4; i++) {
        float inv = 1.f / sden[tm + i];
        size_t base = ((size_t)b * LSEQ + lt * 64 + tm + i) * DMODEL + h * DHEAD + tn;
        __half2 h0 = __floats2half2_rn(acc[i][0]*inv, acc[i][1]*inv);
        __half2 h1 = __floats2half2_rn(acc[i][2]*inv, acc[i][3]*inv);
        *(uint2*)(g_ath + base) = make_uint2(*(uint32_t*)&h0, *(uint32_t*)&h1);
    }
}

// ---------------- launch ------------------------------------------------------
extern "C" void kernel_launch(void* const* d_in, const int* in_sizes, int n_in,
                              void* d_out, int out_size)
{
    const float* x  = (const float*)d_in[0];
    const float* Wq = (const float*)d_in[1];
    const float* Wk = (const float*)d_in[2];
    const float* Wv = (const float*)d_in[3];
    const float* Wo = (const float*)d_in[4];
    float* out = (float*)d_out;

    __half *pXh, *pWth, *pAth;
    cudaGetSymbolAddress((void**)&pXh,  g_xh);
    cudaGetSymbolAddress((void**)&pWth, g_Wth);
    cudaGetSymbolAddress((void**)&pAth, g_ath);

    cudaFuncSetAttribute(gemm_f16_kernel<0>, cudaFuncAttributeMaxDynamicSharedMemorySize, GSMEM);
    cudaFuncSetAttribute(gemm_f16_kernel<1>, cudaFuncAttributeMaxDynamicSharedMemorySize, GSMEM);

    const size_t WN = (size_t)DMODEL * DMODEL;

    // pre-convert operands to fp16 ([N,K] for weights)
    to_half_kernel<<<MROWS * DMODEL / 4 / 256, 256>>>(x, pXh, MROWS * DMODEL / 4);
    transpose_all_kernel<<<dim3(DMODEL / 32, DMODEL / 32, 4), dim3(32, 8)>>>(Wq, Wk, Wv, Wo, pWth);

    // fused QKV GEMM: Bt rows 0..3071 cover Wq|Wk|Wv
    gemm_f16_kernel<1><<<dim3(3 * DMODEL / BN, MROWS / BM), 256, GSMEM>>>(pXh, pWth, nullptr);

    kv_reduce_kernel<<<dim3(NCHUNK, NHEADS, BATCH), 256>>>();
    kv_finalize_kernel<<<(BATCH*NHEADS*DHEAD*DHEAD + 255) / 256, 256>>>();

    attn_apply_kernel<<<dim3(LSEQ / 64, NHEADS, BATCH), 256>>>();

    gemm_f16_kernel<0><<<dim3(DMODEL / BN, MROWS / BM), 256, GSMEM>>>(pAth, pWth + 3 * WN, out);
}

// round 14
// speedup vs baseline: 2.0081x; 1.1000x over previous
#include <cuda_runtime.h>
#include <cuda_fp16.h>
#include <math.h>
#include <stdint.h>

#define BATCH   4
#define LSEQ    8192
#define DMODEL  1024
#define NHEADS  16
#define DHEAD   64
#define MROWS   (BATCH * LSEQ)          // 32768
#define EPSV    1e-6f

// GEMM tiling: CTA 128x128, 8 warps (2x4), warp 64x32, k-stage 32 (fp16).
#define BM      128
#define BN      128
#define KSTG    32
#define NSTG    (DMODEL / KSTG)         // 32
#define RSB     80
#define BOFF    (BM * RSB)
#define STG_B   ((BM + BN) * RSB)       // 20480
#define GSMEM   (4 * STG_B)             // 81920

// kv_reduce (tensor-core) tiling
#define KVCH    16                      // split-K chunks over L
#define KVL     (LSEQ / KVCH)           // 512 rows per CTA
#define KROW    144                     // smem row stride bytes (64 halves + pad)
#define KBUF    (64 * KROW)             // 9216 per array
#define KV_SMEM 66560                   // reduce area (64KB + 1KB) >= 2 load bufs (36.9KB)
#define ONES16  0x3C003C00u

// ---------------- scratch (device globals; no allocations allowed) ----------
static __device__ __half g_xh  [(size_t)MROWS * DMODEL];
static __device__ __half g_Wth [(size_t)4 * DMODEL * DMODEL];           // [N,K] fp16 W (q,k,v,o)
static __device__ __half g_Qfh [(size_t)MROWS * DMODEL];
static __device__ __half g_Kfh [(size_t)MROWS * DMODEL];
static __device__ __half g_Vh  [(size_t)MROWS * DMODEL];
static __device__ __half g_ath [(size_t)MROWS * DMODEL];
static __device__ float  g_KvP [(size_t)KVCH * BATCH * NHEADS * DHEAD * DHEAD];
static __device__ float  g_K1P [(size_t)KVCH * BATCH * NHEADS * DHEAD];
static __device__ float  g_Kv  [(size_t)BATCH * NHEADS * DHEAD * DHEAD];
static __device__ float  g_K1  [(size_t)BATCH * NHEADS * DHEAD];

// ---------------- helpers ----------------------------------------------------
__device__ __forceinline__ uint32_t smem_u32(const void* p) {
    uint32_t a;
    asm("{ .reg .u64 t; cvta.to.shared.u64 t, %1; cvt.u32.u64 %0, t; }" : "=r"(a) : "l"(p));
    return a;
}
__device__ __forceinline__ void cp_async16(uint32_t saddr, const void* gptr) {
    asm volatile("cp.async.cg.shared.global [%0], [%1], 16;" :: "r"(saddr), "l"(gptr));
}
__device__ __forceinline__ void cp_commit() { asm volatile("cp.async.commit_group;"); }
template <int N> __device__ __forceinline__ void cp_wait() {
    asm volatile("cp.async.wait_group %0;" :: "n"(N));
}
__device__ __forceinline__ void mma_f16(float c[4],
                                        uint32_t a0, uint32_t a1, uint32_t a2, uint32_t a3,
                                        uint32_t b0, uint32_t b1)
{
    asm volatile("mma.sync.aligned.m16n8k16.row.col.f32.f16.f16.f32 "
                 "{%0,%1,%2,%3}, {%4,%5,%6,%7}, {%8,%9}, {%0,%1,%2,%3};"
                 : "+f"(c[0]), "+f"(c[1]), "+f"(c[2]), "+f"(c[3])
                 : "r"(a0), "r"(a1), "r"(a2), "r"(a3), "r"(b0), "r"(b1));
}
__device__ __forceinline__ void ldsm_x4(uint32_t& r0, uint32_t& r1, uint32_t& r2, uint32_t& r3,
                                        uint32_t addr)
{
    asm volatile("ldmatrix.sync.aligned.m8n8.x4.shared.b16 {%0,%1,%2,%3}, [%4];"
                 : "=r"(r0), "=r"(r1), "=r"(r2), "=r"(r3) : "r"(addr));
}
__device__ __forceinline__ void ldsm_x4t(uint32_t& r0, uint32_t& r1, uint32_t& r2, uint32_t& r3,
                                         uint32_t addr)
{
    asm volatile("ldmatrix.sync.aligned.m8n8.x4.trans.shared.b16 {%0,%1,%2,%3}, [%4];"
                 : "=r"(r0), "=r"(r1), "=r"(r2), "=r"(r3) : "r"(addr));
}
__device__ __forceinline__ void unpack8(float* dst, uint4 raw)
{
    float2 f;
    f = __half22float2(*(__half2*)&raw.x); dst[0]=f.x; dst[1]=f.y;
    f = __half22float2(*(__half2*)&raw.y); dst[2]=f.x; dst[3]=f.y;
    f = __half22float2(*(__half2*)&raw.z); dst[4]=f.x; dst[5]=f.y;
    f = __half22float2(*(__half2*)&raw.w); dst[6]=f.x; dst[7]=f.y;
}

// ---------------- pre-passes --------------------------------------------------
__global__ void to_half_kernel(const float* __restrict__ in, __half* __restrict__ out, int n4)
{
    int i = blockIdx.x * blockDim.x + threadIdx.x;
    if (i < n4) {
        float4 v = ((const float4*)in)[i];
        __half2 h0 = __floats2half2_rn(v.x, v.y);
        __half2 h1 = __floats2half2_rn(v.z, v.w);
        ((uint2*)out)[i] = make_uint2(*(uint32_t*)&h0, *(uint32_t*)&h1);
    }
}

__global__ void transpose_all_kernel(const float* __restrict__ Wq, const float* __restrict__ Wk,
                                     const float* __restrict__ Wv, const float* __restrict__ Wo,
                                     __half* __restrict__ dst)
{
    __shared__ float t[32][33];
    const float* src = (blockIdx.z == 0) ? Wq : (blockIdx.z == 1) ? Wk
                     : (blockIdx.z == 2) ? Wv : Wo;
    __half* d = dst + (size_t)blockIdx.z * DMODEL * DMODEL;
    const int bx = blockIdx.x * 32, by = blockIdx.y * 32;
    const int tx = threadIdx.x, ty = threadIdx.y;
    #pragma unroll
    for (int j = ty; j < 32; j += 8)
        t[j][tx] = src[(size_t)(by + j) * DMODEL + bx + tx];
    __syncthreads();
    #pragma unroll
    for (int j = ty; j < 32; j += 8)
        d[(size_t)(bx + j) * DMODEL + by + tx] = __float2half_rn(t[tx][j]);
}

// ---------------- fp16 mma.sync GEMM with ldmatrix ---------------------------
template <int MODE>
__global__ __launch_bounds__(256, 2)
void gemm_f16_kernel(const __half* __restrict__ A, const __half* __restrict__ Bt,
                     float* __restrict__ Cf)
{
    extern __shared__ __align__(16) char smc[];
    const uint32_t sb = smem_u32(smc);

    const int tid  = threadIdx.x;
    const int lane = tid & 31;
    const int wid  = tid >> 5;
    const int bm   = blockIdx.y * BM;
    const int bn   = blockIdx.x * BN;
    const int wm   = (wid >> 2) * 64;
    const int wn   = (wid & 3) * 32;

    const int srow = tid >> 2;
    const int sch  = tid & 3;

    auto load_stage = [&](int s) {
        const uint32_t st = sb + (uint32_t)(s & 3) * STG_B;
        const int k0 = s * KSTG + sch * 8;
        cp_async16(st + (uint32_t)srow * RSB + sch * 16,
                   A + (size_t)(bm + srow) * DMODEL + k0);
        cp_async16(st + (uint32_t)(srow + 64) * RSB + sch * 16,
                   A + (size_t)(bm + srow + 64) * DMODEL + k0);
        cp_async16(st + BOFF + (uint32_t)srow * RSB + sch * 16,
                   Bt + (size_t)(bn + srow) * DMODEL + k0);
        cp_async16(st + BOFF + (uint32_t)(srow + 64) * RSB + sch * 16,
                   Bt + (size_t)(bn + srow + 64) * DMODEL + k0);
    };

    const uint32_t a_off = (uint32_t)(wm + ((lane >> 3) & 1) * 8 + (lane & 7)) * RSB
                         + (uint32_t)(lane >> 4) * 16;
    const uint32_t b_off = BOFF + (uint32_t)(wn + (lane >> 4) * 8 + (lane & 7)) * RSB
                         + (uint32_t)((lane >> 3) & 1) * 16;

    float acc[4][4][4];
    #pragma unroll
    for (int mt = 0; mt < 4; mt++)
        #pragma unroll
        for (int nt = 0; nt < 4; nt++)
            #pragma unroll
            for (int i = 0; i < 4; i++) acc[mt][nt][i] = 0.f;

    load_stage(0); cp_commit();
    load_stage(1); cp_commit();
    load_stage(2); cp_commit();

    #pragma unroll 1
    for (int c = 0; c < NSTG; c++) {
        cp_wait<2>();
        __syncthreads();

        if (c + 3 < NSTG) load_stage(c + 3);
        cp_commit();

        const uint32_t st = sb + (uint32_t)(c & 3) * STG_B;
        #pragma unroll
        for (int ks = 0; ks < 2; ks++) {
            const uint32_t ko = (uint32_t)ks * 32;
            uint32_t bfr[4][2];
            ldsm_x4(bfr[0][0], bfr[0][1], bfr[1][0], bfr[1][1], st + b_off + ko);
            ldsm_x4(bfr[2][0], bfr[2][1], bfr[3][0], bfr[3][1], st + b_off + 16 * RSB + ko);
            #pragma unroll
            for (int mt = 0; mt < 4; mt++) {
                uint32_t a0, a1, a2, a3;
                ldsm_x4(a0, a1, a2, a3, st + a_off + mt * (16 * RSB) + ko);
                #pragma unroll
                for (int nt = 0; nt < 4; nt++)
                    mma_f16(acc[mt][nt], a0, a1, a2, a3, bfr[nt][0], bfr[nt][1]);
            }
        }
    }

    const int lr = lane >> 2;
    const int lc = lane & 3;

    if (MODE == 0) {
        #pragma unroll
        for (int mt = 0; mt < 4; mt++)
            #pragma unroll
            for (int nt = 0; nt < 4; nt++) {
                const int row0 = bm + wm + mt * 16 + lr;
                const int col  = bn + wn + nt * 8 + lc * 2;
                *(float2*)(Cf + (size_t)row0 * DMODEL + col) =
                    make_float2(acc[mt][nt][0], acc[mt][nt][1]);
                *(float2*)(Cf + (size_t)(row0 + 8) * DMODEL + col) =
                    make_float2(acc[mt][nt][2], acc[mt][nt][3]);
            }
    } else {
        const int seg = bn >> 10;             // 0=Q, 1=K, 2=V
        const int bnl = bn & 1023;
        __half* outp = (seg == 0) ? g_Qfh : (seg == 1) ? g_Kfh : g_Vh;
        const bool phi = (seg < 2);
        #pragma unroll
        for (int mt = 0; mt < 4; mt++)
            #pragma unroll
            for (int nt = 0; nt < 4; nt++) {
                const int row0 = bm + wm + mt * 16 + lr;
                const int col  = bnl + wn + nt * 8 + lc * 2;
                float v[4];
                #pragma unroll
                for (int i = 0; i < 4; i++) {
                    float t = acc[mt][nt][i];
                    if (phi) t = (t > 0.f) ? (t + 1.f) : __expf(t);
                    v[i] = t;
                }
                __half2 h0 = __floats2half2_rn(v[0], v[1]);
                __half2 h1 = __floats2half2_rn(v[2], v[3]);
                *(uint32_t*)(outp + (size_t)row0 * DMODEL + col)       = *(uint32_t*)&h0;
                *(uint32_t*)(outp + (size_t)(row0 + 8) * DMODEL + col) = *(uint32_t*)&h1;
            }
    }
}

// ---------------- Kv / K1 reduction on tensor cores ---------------------------
// Per (chunk,h,b): Kv_part[64,64] = Kf[l0:l0+512, head]^T @ V[l0:l0+512, head]
// 8 warps = 2 m-groups x 4 l-groups; per 64-row subtile each warp does one k16
// slab (A = Kf^T, B = V^T via ldmatrix.trans). K1 via extra MMA against ones.
__global__ __launch_bounds__(256, 2)
void kv_reduce_mma_kernel()
{
    extern __shared__ __align__(16) char km[];
    const uint32_t sb = smem_u32(km);
    const int tid  = threadIdx.x;
    const int lane = tid & 31;
    const int wid  = tid >> 5;
    const int chunk = blockIdx.x;
    const int h     = blockIdx.y;
    const int b     = blockIdx.z;
    const int bh    = b * NHEADS + h;
    const int mg = wid & 1;              // m 0-31 / 32-63
    const int lg = wid >> 1;             // k16 slab within 64-row subtile
    const int lb = lg * 16;

    auto load_sub = [&](int sub, int buf) {
        const uint32_t base = sb + (uint32_t)buf * (2 * KBUF);
        const int l0 = chunk * KVL + sub * 64;
        #pragma unroll
        for (int i = 0; i < 2; i++) {
            const int idx = tid + i * 256;
            const int row = idx >> 3, ch = idx & 7;
            size_t g = ((size_t)b * LSEQ + l0 + row) * DMODEL + h * DHEAD + ch * 8;
            cp_async16(base + (uint32_t)row * KROW + ch * 16,        g_Kfh + g);
            cp_async16(base + KBUF + (uint32_t)row * KROW + ch * 16, g_Vh + g);
        }
    };

    // A (.trans): octets (l0-7,m0-7),(l0-7,m8-15),(l8-15,m0-7),(l8-15,m8-15)
    //   row += 8 for octets 2,3 (lane>>4); col += 8 for odd octets ((lane>>3)&1)
    const uint32_t a_lane = (uint32_t)(lb + (lane >> 4) * 8 + (lane & 7)) * KROW
                          + (uint32_t)((lane >> 3) & 1) * 16;
    // B (.trans): octets (l0-7,n0-7),(l8-15,n0-7),(l0-7,n8-15),(l8-15,n8-15)
    //   row += 8 for odd octets; col += 8 for octets 2,3
    const uint32_t b_lane = KBUF + (uint32_t)(lb + ((lane >> 3) & 1) * 8 + (lane & 7)) * KROW
                          + (uint32_t)(lane >> 4) * 16;

    float accK[2][8][4];
    float accS[2][4];
    #pragma unroll
    for (int mt = 0; mt < 2; mt++) {
        #pragma unroll
        for (int nt = 0; nt < 8; nt++)
            #pragma unroll
            for (int i = 0; i < 4; i++) accK[mt][nt][i] = 0.f;
        #pragma unroll
        for (int i = 0; i < 4; i++) accS[mt][i] = 0.f;
    }

    load_sub(0, 0); cp_commit();

    #pragma unroll 1
    for (int sub = 0; sub < 8; sub++) {
        if (sub < 7) { load_sub(sub + 1, (sub + 1) & 1); cp_commit(); cp_wait<1>(); }
        else         { cp_wait<0>(); }
        __syncthreads();

        const uint32_t base = sb + (uint32_t)(sub & 1) * (2 * KBUF);
        uint32_t bfr[8][2];
        #pragma unroll
        for (int p = 0; p < 4; p++)
            ldsm_x4t(bfr[2*p][0], bfr[2*p][1], bfr[2*p+1][0], bfr[2*p+1][1],
                     base + b_lane + (uint32_t)p * 32);
        #pragma unroll
        for (int mt = 0; mt < 2; mt++) {
            uint32_t a0, a1, a2, a3;
            ldsm_x4t(a0, a1, a2, a3, base + a_lane + (uint32_t)(mg * 32 + mt * 16) * 2);
            #pragma unroll
            for (int nt = 0; nt < 8; nt++)
                mma_f16(accK[mt][nt], a0, a1, a2, a3, bfr[nt][0], bfr[nt][1]);
            mma_f16(accS[mt], a0, a1, a2, a3, ONES16, ONES16);   // K1 = row sums
        }
        __syncthreads();   // protect buffer reuse two iterations ahead
    }

    // ---- cross-lg reduction through smem ----
    float* red   = (float*)km;             // [4][64][64]
    float* redk1 = (float*)(km + 65536);   // [4][64]
    const int lr = lane >> 2;
    const int lc = lane & 3;
    #pragma unroll
    for (int mt = 0; mt < 2; mt++) {
        const int m = mg * 32 + mt * 16 + lr;
        #pragma unroll
        for (int nt = 0; nt < 8; nt++) {
            const int n = nt * 8 + lc * 2;
            *(float2*)&red[((lg * 64 + m) * 64) + n]     = make_float2(accK[mt][nt][0], accK[mt][nt][1]);
            *(float2*)&red[((lg * 64 + m + 8) * 64) + n] = make_float2(accK[mt][nt][2], accK[mt][nt][3]);
        }
        if (lc == 0) {
            redk1[lg * 64 + m]     = accS[mt][0];
            redk1[lg * 64 + m + 8] = accS[mt][2];
        }
    }
    __syncthreads();

    for (int i = tid; i < 4096; i += 256) {
        float s = red[i] + red[4096 + i] + red[8192 + i] + red[12288 + i];
        g_KvP[((size_t)chunk * (BATCH * NHEADS) + bh) * 4096 + i] = s;
    }
    if (tid < 64) {
        float s = redk1[tid] + redk1[64 + tid] + redk1[128 + tid] + redk1[192 + tid];
        g_K1P[((size_t)chunk * (BATCH * NHEADS) + bh) * 64 + tid] = s;
    }
}

__global__ void kv_finalize_kernel()
{
    const int i = blockIdx.x * blockDim.x + threadIdx.x;
    const int KV_ELEMS = BATCH * NHEADS * DHEAD * DHEAD;
    const int K1_ELEMS = BATCH * NHEADS * DHEAD;
    if (i < KV_ELEMS) {
        float s = 0.f;
        #pragma unroll
        for (int c = 0; c < KVCH; c++) s += g_KvP[(size_t)c * KV_ELEMS + i];
        g_Kv[i] = s;
    }
    if (i < K1_ELEMS) {
        float s = 0.f;
        #pragma unroll
        for (int c = 0; c < KVCH; c++) s += g_K1P[(size_t)c * K1_ELEMS + i];
        g_K1[i] = s;
    }
}

// ---------------- apply: attn = (Qf @ Kv) / (Qf @ K1 + eps) -> fp16 ----------
__global__ __launch_bounds__(256, 4)
void attn_apply_kernel()
{
    const int lt = blockIdx.x;
    const int h  = blockIdx.y;
    const int b  = blockIdx.z;
    const int bh = b * NHEADS + h;
    const int tid = threadIdx.x;

    __shared__ float sQ [64][65];
    __shared__ float sKv[64][65];
    __shared__ float sK1[64];
    __shared__ float sden[64];

    for (int i = tid; i < 64 * 8; i += 256) {
        int r  = i >> 3;
        int c8 = (i & 7) << 3;
        size_t qbase = ((size_t)b * LSEQ + lt * 64 + r) * DMODEL + h * DHEAD + c8;
        unpack8(&sQ[r][c8], *(const uint4*)(g_Qfh + qbase));
    }
    for (int i = tid; i < 64 * 16; i += 256) {
        int r  = i >> 4;
        int c4 = (i & 15) << 2;
        float4 kv = *(const float4*)(g_Kv + ((size_t)bh * DHEAD + r) * DHEAD + c4);
        sKv[r][c4+0]=kv.x; sKv[r][c4+1]=kv.y; sKv[r][c4+2]=kv.z; sKv[r][c4+3]=kv.w;
    }
    if (tid < 64) sK1[tid] = g_K1[(size_t)bh * DHEAD + tid];
    __syncthreads();

    if (tid < 64) {
        float d = 0.f;
        #pragma unroll
        for (int m = 0; m < 64; m++) d += sQ[tid][m] * sK1[m];
        sden[tid] = d + EPSV;
    }
    __syncthreads();

    const int tm = (tid >> 4) * 4;
    const int tn = (tid & 15) * 4;
    float acc[4][4];
    #pragma unroll
    for (int i = 0; i < 4; i++)
        #pragma unroll
        for (int j = 0; j < 4; j++) acc[i][j] = 0.f;

    #pragma unroll 4
    for (int m = 0; m < 64; m++) {
        float a0 = sQ[tm+0][m], a1 = sQ[tm+1][m], a2 = sQ[tm+2][m], a3 = sQ[tm+3][m];
        float b0 = sKv[m][tn+0], b1 = sKv[m][tn+1], b2 = sKv[m][tn+2], b3 = sKv[m][tn+3];
        acc[0][0]+=a0*b0; acc[0][1]+=a0*b1; acc[0][2]+=a0*b2; acc[0][3]+=a0*b3;
        acc[1][0]+=a1*b0; acc[1][1]+=a1*b1; acc[1][2]+=a1*b2; acc[1][3]+=a1*b3;
        acc[2][0]+=a2*b0; acc[2][1]+=a2*b1; acc[2][2]+=a2*b2; acc[2][3]+=a2*b3;
        acc[3][0]+=a3*b0; acc[3][1]+=a3*b1; acc[3][2]+=a3*b2; acc[3][3]+=a3*b3;
    }

    #pragma unroll
    for (int i = 0; i < 4; i++) {
        float inv = 1.f / sden[tm + i];
        size_t base = ((size_t)b * LSEQ + lt * 64 + tm + i) * DMODEL + h * DHEAD + tn;
        __half2 h0 = __floats2half2_rn(acc[i][0]*inv, acc[i][1]*inv);
        __half2 h1 = __floats2half2_rn(acc[i][2]*inv, acc[i][3]*inv);
        *(uint2*)(g_ath + base) = make_uint2(*(uint32_t*)&h0, *(uint32_t*)&h1);
    }
}

// ---------------- launch ------------------------------------------------------
extern "C" void kernel_launch(void* const* d_in, const int* in_sizes, int n_in,
                              void* d_out, int out_size)
{
    const float* x  = (const float*)d_in[0];
    const float* Wq = (const float*)d_in[1];
    const float* Wk = (const float*)d_in[2];
    const float* Wv = (const float*)d_in[3];
    const float* Wo = (const float*)d_in[4];
    float* out = (float*)d_out;

    __half *pXh, *pWth, *pAth;
    cudaGetSymbolAddress((void**)&pXh,  g_xh);
    cudaGetSymbolAddress((void**)&pWth, g_Wth);
    cudaGetSymbolAddress((void**)&pAth, g_ath);

    cudaFuncSetAttribute(gemm_f16_kernel<0>, cudaFuncAttributeMaxDynamicSharedMemorySize, GSMEM);
    cudaFuncSetAttribute(gemm_f16_kernel<1>, cudaFuncAttributeMaxDynamicSharedMemorySize, GSMEM);
    cudaFuncSetAttribute(kv_reduce_mma_kernel, cudaFuncAttributeMaxDynamicSharedMemorySize, KV_SMEM);

    const size_t WN = (size_t)DMODEL * DMODEL;

    to_half_kernel<<<MROWS * DMODEL / 4 / 256, 256>>>(x, pXh, MROWS * DMODEL / 4);
    transpose_all_kernel<<<dim3(DMODEL / 32, DMODEL / 32, 4), dim3(32, 8)>>>(Wq, Wk, Wv, Wo, pWth);

    // fused QKV GEMM
    gemm_f16_kernel<1><<<dim3(3 * DMODEL / BN, MROWS / BM), 256, GSMEM>>>(pXh, pWth, nullptr);

    kv_reduce_mma_kernel<<<dim3(KVCH, NHEADS, BATCH), 256, KV_SMEM>>>();
    kv_finalize_kernel<<<(BATCH*NHEADS*DHEAD*DHEAD + 255) / 256, 256>>>();

    attn_apply_kernel<<<dim3(LSEQ / 64, NHEADS, BATCH), 256>>>();

    gemm_f16_kernel<0><<<dim3(DMODEL / BN, MROWS / BM), 256, GSMEM>>>(pAth, pWth + 3 * WN, out);
}